// round 14
// baseline (speedup 1.0000x reference)
#include <cuda_runtime.h>

// Problem constants (fixed shape for this problem)
#define N_NODES 131072
#define LVL     16
#define P       8192
#define D       128
#define KE      8
#define PK      (P*KE)     // 65536
#define LM1     (LVL-1)    // 15

// -------- scratch (static __device__ — no allocation allowed) --------
__device__ float g_h [(size_t)N_NODES * D];  // node_transform output (64MB)
__device__ float g_mf[(size_t)P * D];        // forward per-level message rows
__device__ float g_mb[(size_t)P * D];        // backward per-level message rows
__device__ int   g_deg [LM1 * P];
__device__ int   g_off [LM1 * P];
__device__ int   g_cur [LM1 * P];
__device__ float g_rdeg[LM1 * P];
__device__ int   g_rev [LM1 * PK];

// -------- packed f32x2 helpers (Blackwell FFMA2 via PTX only) --------
__device__ __forceinline__ unsigned long long pack2(float x, float y) {
    unsigned long long r;
    asm("mov.b64 %0, {%1, %2};" : "=l"(r) : "f"(x), "f"(y));
    return r;
}
__device__ __forceinline__ void up2(unsigned long long v, float& x, float& y) {
    asm("mov.b64 {%0, %1}, %2;" : "=f"(x), "=f"(y) : "l"(v));
}
__device__ __forceinline__ unsigned long long ffma2(unsigned long long a,
                                                    unsigned long long b,
                                                    unsigned long long c) {
    unsigned long long d;
    asm("fma.rn.f32x2 %0, %1, %2, %3;" : "=l"(d) : "l"(a), "l"(b), "l"(c));
    return d;
}

// -------- shared GEMM core: [MTILE x 128] = sA[MTILE x 128] @ sW[128 x 128] --------
// thread grid 16(ty) x 16(tx), thread tile RPT rows x 8 cols (as 4 f32x2 pairs)
template<int RPT>
__device__ __forceinline__ void gemm_tile(const float* __restrict__ sA,
                                          const float* __restrict__ sW,
                                          int ty, int tx,
                                          unsigned long long acc[RPT][4]) {
#pragma unroll
    for (int i = 0; i < RPT; i++) {
        acc[i][0] = 0ull; acc[i][1] = 0ull; acc[i][2] = 0ull; acc[i][3] = 0ull;
    }
    const float* aBase = sA + (ty * RPT) * 128;
    const float* wBase = sW + tx * 8;
#pragma unroll 2
    for (int k = 0; k < 128; k += 4) {
        float4 av[RPT];
#pragma unroll
        for (int i = 0; i < RPT; i++)
            av[i] = *(const float4*)(aBase + i * 128 + k);
#pragma unroll
        for (int kk = 0; kk < 4; kk++) {
            const float* wr = wBase + (k + kk) * 128;
            ulonglong2 b01 = *(const ulonglong2*)(wr);
            ulonglong2 b23 = *(const ulonglong2*)(wr + 4);
#pragma unroll
            for (int i = 0; i < RPT; i++) {
                float a = (kk == 0) ? av[i].x : (kk == 1) ? av[i].y
                         : (kk == 2) ? av[i].z : av[i].w;
                unsigned long long aa = pack2(a, a);
                acc[i][0] = ffma2(aa, b01.x, acc[i][0]);
                acc[i][1] = ffma2(aa, b01.y, acc[i][1]);
                acc[i][2] = ffma2(aa, b23.x, acc[i][2]);
                acc[i][3] = ffma2(aa, b23.y, acc[i][3]);
            }
        }
    }
}

// ================= CSR build (once per call, replayed in graph) =================
__global__ void zero_kernel() {
    int i = blockIdx.x * blockDim.x + threadIdx.x;
    if (i < LM1 * P) g_deg[i] = 0;
}
__global__ void count_kernel(const int* __restrict__ src) {
    int e = blockIdx.x * blockDim.x + threadIdx.x;
    if (e < LM1 * PK) {
        int l = e >> 16;              // PK = 65536
        atomicAdd(&g_deg[l * P + src[e]], 1);
    }
}
__global__ void scan_kernel() {
    int l = blockIdx.x, t = threadIdx.x;   // 256 threads, 8192 entries
    __shared__ int ss[256];
    int base = l * P + t * 32;
    int loc[32]; int s = 0;
#pragma unroll
    for (int i = 0; i < 32; i++) { loc[i] = g_deg[base + i]; s += loc[i]; }
    ss[t] = s; __syncthreads();
    if (t == 0) { int run = 0; for (int i = 0; i < 256; i++) { int v = ss[i]; ss[i] = run; run += v; } }
    __syncthreads();
    int run = ss[t];
#pragma unroll
    for (int i = 0; i < 32; i++) {
        g_off[base + i] = run;
        g_cur[base + i] = run;
        int d = loc[i];
        g_rdeg[base + i] = 1.0f / (float)(d > 0 ? d : 1);
        run += d;
    }
}
__global__ void fill_kernel(const int* __restrict__ src) {
    int e = blockIdx.x * blockDim.x + threadIdx.x;
    if (e < LM1 * PK) {
        int l = e >> 16, le = e & 65535;
        int slot = atomicAdd(&g_cur[l * P + src[e]], 1);
        g_rev[l * PK + slot] = le >> 3;   // dst node = edge/K
    }
}

// ================= node transform: h = relu(x@W1+b1)@W2+b2 =================
// also writes out level-0 forward init and level-(L-1) backward init
__global__ void __launch_bounds__(256, 1)
nt_kernel(const float* __restrict__ x,
          const float* __restrict__ w1, const float* __restrict__ b1,
          const float* __restrict__ w2, const float* __restrict__ b2,
          const float* __restrict__ fub, const float* __restrict__ bub,
          float* __restrict__ out) {
    extern __shared__ float sm[];
    float* sW1 = sm;                 // 16384
    float* sW2 = sm + 16384;         // 16384
    float* sT  = sm + 32768;         // 16384 (x tile, then hidden tile)
    float* sB1 = sm + 49152;
    float* sB2 = sB1 + 128;
    float* sFb = sB2 + 128;
    float* sBb = sFb + 128;
    int tid = threadIdx.x;
    int row0 = blockIdx.x * 128;

    for (int i = tid; i < 4096; i += 256) {
        ((float4*)sW1)[i] = ((const float4*)w1)[i];
        ((float4*)sW2)[i] = ((const float4*)w2)[i];
        ((float4*)sT)[i]  = ((const float4*)x)[(size_t)row0 * 32 + i];
    }
    if (tid < 128) {
        sB1[tid] = b1[tid]; sB2[tid] = b2[tid];
        float f = fub[tid]; sFb[tid] = f > 0.f ? f : 0.f;
        float g = bub[tid]; sBb[tid] = g > 0.f ? g : 0.f;
    }
    __syncthreads();

    int ty = tid >> 4, tx = tid & 15;
    unsigned long long acc[8][4];
    gemm_tile<8>(sT, sW1, ty, tx, acc);
    __syncthreads();                  // everyone done reading x tile
#pragma unroll
    for (int i = 0; i < 8; i++) {
        int r = ty * 8 + i;
#pragma unroll
        for (int j = 0; j < 4; j++) {
            float lo, hi; up2(acc[i][j], lo, hi);
            int c = tx * 8 + 2 * j;
            lo += sB1[c]; hi += sB1[c + 1];
            sT[r * 128 + c]     = lo > 0.f ? lo : 0.f;
            sT[r * 128 + c + 1] = hi > 0.f ? hi : 0.f;
        }
    }
    __syncthreads();
    gemm_tile<8>(sT, sW2, ty, tx, acc);

    bool first = (row0 < P);
    bool last  = (row0 >= N_NODES - P);
#pragma unroll
    for (int i = 0; i < 8; i++) {
        int g = row0 + ty * 8 + i;
#pragma unroll
        for (int j = 0; j < 4; j++) {
            float lo, hi; up2(acc[i][j], lo, hi);
            int c = tx * 8 + 2 * j;
            lo += sB2[c]; hi += sB2[c + 1];
            *(float2*)&g_h[(size_t)g * 128 + c] = make_float2(lo, hi);
            if (first)
                *(float2*)&out[(size_t)g * 256 + c] = make_float2(lo + sFb[c], hi + sFb[c + 1]);
            if (last)
                *(float2*)&out[(size_t)g * 256 + 128 + c] = make_float2(lo + sBb[c], hi + sBb[c + 1]);
        }
    }
}

// ================= m = relu(Y @ pre_w + pre_b), Y strided in out =================
__global__ void __launch_bounds__(256, 2)
pre_kernel(const float* __restrict__ yin,   // out + level_base*256 (+128 for bwd)
           const float* __restrict__ W, const float* __restrict__ bias,
           int dir) {                        // 0 -> g_mf, 1 -> g_mb
    extern __shared__ float sm[];
    float* sW = sm;            // 16384
    float* sA = sm + 16384;    // 8192
    float* sB = sm + 24576;    // 128
    int tid = threadIdx.x;
    int row0 = blockIdx.x * 64;

    for (int i = tid; i < 4096; i += 256) ((float4*)sW)[i] = ((const float4*)W)[i];
    for (int i = tid; i < 2048; i += 256) {
        int r = i >> 5, c = i & 31;
        ((float4*)sA)[i] = *(const float4*)(yin + (size_t)(row0 + r) * 256 + c * 4);
    }
    if (tid < 128) sB[tid] = bias[tid];
    __syncthreads();

    int ty = tid >> 4, tx = tid & 15;
    unsigned long long acc[4][4];
    gemm_tile<4>(sA, sW, ty, tx, acc);
    float* mo = dir ? g_mb : g_mf;
#pragma unroll
    for (int i = 0; i < 4; i++) {
        int r = row0 + ty * 4 + i;
#pragma unroll
        for (int j = 0; j < 4; j++) {
            float lo, hi; up2(acc[i][j], lo, hi);
            int c = tx * 8 + 2 * j;
            lo += sB[c]; hi += sB[c + 1];
            lo = lo > 0.f ? lo : 0.f; hi = hi > 0.f ? hi : 0.f;
            *(float2*)&mo[(size_t)r * 128 + c] = make_float2(lo, hi);
        }
    }
}

// ================= forward update: gather-mean(m_f) -> GEMM -> +h =================
__global__ void __launch_bounds__(256, 2)
updf_kernel(const int* __restrict__ srcl,    // src + (l-1)*PK
            const float* __restrict__ W, const float* __restrict__ bias,
            int level, float* __restrict__ outp) {   // outp = out + level*P*256
    extern __shared__ float sm[];
    float* sW = sm; float* sZ = sm + 16384; float* sB = sm + 24576;
    int* sSrc = (int*)(sm + 24704);          // 512 ints
    int tid = threadIdx.x;
    int row0 = blockIdx.x * 64;

    for (int i = tid; i < 4096; i += 256) ((float4*)sW)[i] = ((const float4*)W)[i];
    if (tid < 128) sB[tid] = bias[tid];
    for (int i = tid; i < 512; i += 256) sSrc[i] = srcl[row0 * 8 + i];
    __syncthreads();

    for (int idx = tid; idx < 8192; idx += 256) {
        int r = idx >> 7, c = idx & 127;
        const int* s8 = sSrc + r * 8;
        float v = 0.f;
#pragma unroll
        for (int k = 0; k < 8; k++) v += g_mf[(size_t)s8[k] * 128 + c];
        sZ[idx] = v * 0.125f;
    }
    __syncthreads();

    int ty = tid >> 4, tx = tid & 15;
    unsigned long long acc[4][4];
    gemm_tile<4>(sZ, sW, ty, tx, acc);
    const float* hrow = g_h + (size_t)level * P * 128;
#pragma unroll
    for (int i = 0; i < 4; i++) {
        int r = row0 + ty * 4 + i;
#pragma unroll
        for (int j = 0; j < 4; j++) {
            float lo, hi; up2(acc[i][j], lo, hi);
            int c = tx * 8 + 2 * j;
            lo += sB[c]; hi += sB[c + 1];
            lo = lo > 0.f ? lo : 0.f; hi = hi > 0.f ? hi : 0.f;
            float2 h2 = *(const float2*)&hrow[(size_t)r * 128 + c];
            *(float2*)&outp[(size_t)r * 256 + c] = make_float2(lo + h2.x, hi + h2.y);
        }
    }
}

// ================= backward update: CSR gather-mean(m_b) -> GEMM -> +h =================
__global__ void __launch_bounds__(256, 2)
updb_kernel(const float* __restrict__ W, const float* __restrict__ bias,
            int level, float* __restrict__ outp) {   // outp = out + level*P*256 + 128
    extern __shared__ float sm[];
    float* sW = sm; float* sZ = sm + 16384; float* sB = sm + 24576;
    int* sSt = (int*)(sm + 24704); int* sCnt = sSt + 64; float* sRd = (float*)(sCnt + 64);
    int tid = threadIdx.x;
    int row0 = blockIdx.x * 64;

    for (int i = tid; i < 4096; i += 256) ((float4*)sW)[i] = ((const float4*)W)[i];
    if (tid < 128) sB[tid] = bias[tid];
    if (tid < 64) {
        int g = level * P + row0 + tid;
        sSt[tid] = g_off[g]; sCnt[tid] = g_deg[g]; sRd[tid] = g_rdeg[g];
    }
    __syncthreads();

    const int* rev = g_rev + (size_t)level * PK;
    for (int idx = tid; idx < 8192; idx += 256) {
        int r = idx >> 7, c = idx & 127;
        int st = sSt[r], n = sCnt[r];
        float v = 0.f;
        for (int j = 0; j < n; j++) v += g_mb[(size_t)rev[st + j] * 128 + c];
        sZ[idx] = v * sRd[r];
    }
    __syncthreads();

    int ty = tid >> 4, tx = tid & 15;
    unsigned long long acc[4][4];
    gemm_tile<4>(sZ, sW, ty, tx, acc);
    const float* hrow = g_h + (size_t)level * P * 128;
#pragma unroll
    for (int i = 0; i < 4; i++) {
        int r = row0 + ty * 4 + i;
#pragma unroll
        for (int j = 0; j < 4; j++) {
            float lo, hi; up2(acc[i][j], lo, hi);
            int c = tx * 8 + 2 * j;
            lo += sB[c]; hi += sB[c + 1];
            lo = lo > 0.f ? lo : 0.f; hi = hi > 0.f ? hi : 0.f;
            float2 h2 = *(const float2*)&hrow[(size_t)r * 128 + c];
            *(float2*)&outp[(size_t)r * 256 + c] = make_float2(lo + h2.x, hi + h2.y);
        }
    }
}

// ================= launch =================
#define NT_SMEM   198656
#define PRE_SMEM   98816
#define UPDF_SMEM 100864
#define UPDB_SMEM  99584

extern "C" void kernel_launch(void* const* d_in, const int* in_sizes, int n_in,
                              void* d_out, int out_size) {
    (void)in_sizes; (void)n_in; (void)out_size;
    const float* x      = (const float*)d_in[0];
    const int*   src    = (const int*)  d_in[1];
    const float* nt_w1  = (const float*)d_in[2];
    const float* nt_b1  = (const float*)d_in[3];
    const float* nt_w2  = (const float*)d_in[4];
    const float* nt_b2  = (const float*)d_in[5];
    const float* f_pre_w= (const float*)d_in[6];
    const float* f_pre_b= (const float*)d_in[7];
    const float* f_upd_w= (const float*)d_in[8];
    const float* f_upd_b= (const float*)d_in[9];
    const float* b_pre_w= (const float*)d_in[10];
    const float* b_pre_b= (const float*)d_in[11];
    const float* b_upd_w= (const float*)d_in[12];
    const float* b_upd_b= (const float*)d_in[13];
    float* out = (float*)d_out;

    cudaFuncSetAttribute(nt_kernel,   cudaFuncAttributeMaxDynamicSharedMemorySize, NT_SMEM);
    cudaFuncSetAttribute(pre_kernel,  cudaFuncAttributeMaxDynamicSharedMemorySize, PRE_SMEM);
    cudaFuncSetAttribute(updf_kernel, cudaFuncAttributeMaxDynamicSharedMemorySize, UPDF_SMEM);
    cudaFuncSetAttribute(updb_kernel, cudaFuncAttributeMaxDynamicSharedMemorySize, UPDB_SMEM);

    // inverse-CSR build (ints only; deterministic sums up to bucket order)
    zero_kernel <<<480, 256>>>();
    count_kernel<<<3840, 256>>>(src);
    scan_kernel <<<LM1, 256>>>();
    fill_kernel <<<3840, 256>>>(src);

    // node transform + level-0 fwd init + level-15 bwd init
    nt_kernel<<<1024, 256, NT_SMEM>>>(x, nt_w1, nt_b1, nt_w2, nt_b2,
                                      f_upd_b, b_upd_b, out);

    // message passing: 15 forward (1..15) and 15 backward (14..0) levels
    for (int i = 0; i < 15; i++) {
        int lf = i + 1, lb = 14 - i;
        pre_kernel <<<128, 256, PRE_SMEM >>>(out + (size_t)(lf - 1) * P * 256,
                                             f_pre_w, f_pre_b, 0);
        updf_kernel<<<128, 256, UPDF_SMEM>>>(src + (size_t)(lf - 1) * PK,
                                             f_upd_w, f_upd_b, lf,
                                             out + (size_t)lf * P * 256);
        pre_kernel <<<128, 256, PRE_SMEM >>>(out + (size_t)(lb + 1) * P * 256 + 128,
                                             b_pre_w, b_pre_b, 1);
        updb_kernel<<<128, 256, UPDB_SMEM>>>(b_upd_w, b_upd_b, lb,
                                             out + (size_t)lb * P * 256 + 128);
    }
}

// round 15
// speedup vs baseline: 1.6574x; 1.6574x over previous
#include <cuda_runtime.h>

// Problem constants (fixed shape for this problem)
#define N_NODES 131072
#define LVL     16
#define P       8192
#define D       128
#define KE      8
#define PK      (P*KE)     // 65536
#define LM1     (LVL-1)    // 15

// -------- scratch (static __device__ — no allocation allowed) --------
__device__ float g_h [(size_t)N_NODES * D];  // hidden, then node_transform output
__device__ float g_mf[(size_t)P * D];        // forward per-level message rows
__device__ float g_mb[(size_t)P * D];        // backward per-level message rows
__device__ int   g_deg [LM1 * P];
__device__ int   g_off [LM1 * P];
__device__ int   g_cur [LM1 * P];
__device__ float g_rdeg[LM1 * P];
__device__ int   g_rev [LM1 * PK];

// -------- packed f32x2 helpers (Blackwell FFMA2 via PTX only) --------
__device__ __forceinline__ unsigned long long pack2(float x, float y) {
    unsigned long long r;
    asm("mov.b64 %0, {%1, %2};" : "=l"(r) : "f"(x), "f"(y));
    return r;
}
__device__ __forceinline__ void up2(unsigned long long v, float& x, float& y) {
    asm("mov.b64 {%0, %1}, %2;" : "=f"(x), "=f"(y) : "l"(v));
}
__device__ __forceinline__ unsigned long long ffma2(unsigned long long a,
                                                    unsigned long long b,
                                                    unsigned long long c) {
    unsigned long long d;
    asm("fma.rn.f32x2 %0, %1, %2, %3;" : "=l"(d) : "l"(a), "l"(b), "l"(c));
    return d;
}

// -------- shared GEMM core: tile[ROWS x 128] = sA[ROWS x 128] @ sW[128 x 128] --------
// thread layout: ty in [0, ROWS/RPT), tx in [0,16); each thread RPT rows x 8 cols
template<int RPT>
__device__ __forceinline__ void gemm_tile(const float* __restrict__ sA,
                                          const float* __restrict__ sW,
                                          int ty, int tx,
                                          unsigned long long acc[RPT][4]) {
#pragma unroll
    for (int i = 0; i < RPT; i++) {
        acc[i][0] = 0ull; acc[i][1] = 0ull; acc[i][2] = 0ull; acc[i][3] = 0ull;
    }
    const float* aBase = sA + (ty * RPT) * 128;
    const float* wBase = sW + tx * 8;
#pragma unroll 2
    for (int k = 0; k < 128; k += 4) {
        float4 av[RPT];
#pragma unroll
        for (int i = 0; i < RPT; i++)
            av[i] = *(const float4*)(aBase + i * 128 + k);
#pragma unroll
        for (int kk = 0; kk < 4; kk++) {
            const float* wr = wBase + (k + kk) * 128;
            ulonglong2 b01 = *(const ulonglong2*)(wr);
            ulonglong2 b23 = *(const ulonglong2*)(wr + 4);
#pragma unroll
            for (int i = 0; i < RPT; i++) {
                float a = (kk == 0) ? av[i].x : (kk == 1) ? av[i].y
                         : (kk == 2) ? av[i].z : av[i].w;
                unsigned long long aa = pack2(a, a);
                acc[i][0] = ffma2(aa, b01.x, acc[i][0]);
                acc[i][1] = ffma2(aa, b01.y, acc[i][1]);
                acc[i][2] = ffma2(aa, b23.x, acc[i][2]);
                acc[i][3] = ffma2(aa, b23.y, acc[i][3]);
            }
        }
    }
}

// ================= CSR build (once per call, replayed in graph) =================
__global__ void zero_kernel() {
    int i = blockIdx.x * blockDim.x + threadIdx.x;
    if (i < LM1 * P) g_deg[i] = 0;
}
__global__ void count_kernel(const int* __restrict__ src) {
    int e = blockIdx.x * blockDim.x + threadIdx.x;
    if (e < LM1 * PK) {
        int l = e >> 16;              // PK = 65536
        atomicAdd(&g_deg[l * P + src[e]], 1);
    }
}
__global__ void scan_kernel() {
    int l = blockIdx.x, t = threadIdx.x;   // 256 threads, 8192 entries
    __shared__ int ss[256];
    int base = l * P + t * 32;
    int loc[32]; int s = 0;
#pragma unroll
    for (int i = 0; i < 32; i++) { loc[i] = g_deg[base + i]; s += loc[i]; }
    ss[t] = s; __syncthreads();
    if (t == 0) { int run = 0; for (int i = 0; i < 256; i++) { int v = ss[i]; ss[i] = run; run += v; } }
    __syncthreads();
    int run = ss[t];
#pragma unroll
    for (int i = 0; i < 32; i++) {
        g_off[base + i] = run;
        g_cur[base + i] = run;
        int d = loc[i];
        g_rdeg[base + i] = 1.0f / (float)(d > 0 ? d : 1);
        run += d;
    }
}
__global__ void fill_kernel(const int* __restrict__ src) {
    int e = blockIdx.x * blockDim.x + threadIdx.x;
    if (e < LM1 * PK) {
        int l = e >> 16, le = e & 65535;
        int slot = atomicAdd(&g_cur[l * P + src[e]], 1);
        g_rev[l * PK + slot] = le >> 3;   // dst node = edge/K
    }
}

// ================= nt pass 1: g_h = relu(x @ W1 + b1) =================
__global__ void __launch_bounds__(128, 2)
nt1_kernel(const float* __restrict__ x,
           const float* __restrict__ w1, const float* __restrict__ b1) {
    extern __shared__ float sm[];
    float* sW = sm;            // 16384
    float* sA = sm + 16384;    // 8192
    float* sB = sm + 24576;    // 128
    int tid = threadIdx.x;
    int row0 = blockIdx.x * 64;

    for (int i = tid; i < 4096; i += 128) ((float4*)sW)[i] = ((const float4*)w1)[i];
    for (int i = tid; i < 2048; i += 128)
        ((float4*)sA)[i] = ((const float4*)x)[(size_t)row0 * 32 + i];
    sB[tid] = b1[tid];
    __syncthreads();

    int ty = tid >> 4, tx = tid & 15;
    unsigned long long acc[8][4];
    gemm_tile<8>(sA, sW, ty, tx, acc);
#pragma unroll
    for (int i = 0; i < 8; i++) {
        int r = row0 + ty * 8 + i;
#pragma unroll
        for (int j = 0; j < 4; j++) {
            float lo, hi; up2(acc[i][j], lo, hi);
            int c = tx * 8 + 2 * j;
            lo += sB[c]; hi += sB[c + 1];
            lo = lo > 0.f ? lo : 0.f; hi = hi > 0.f ? hi : 0.f;
            *(float2*)&g_h[(size_t)r * 128 + c] = make_float2(lo, hi);
        }
    }
}

// ================= nt pass 2: g_h = g_h @ W2 + b2 (in place), plus out inits =================
__global__ void __launch_bounds__(128, 2)
nt2_kernel(const float* __restrict__ w2, const float* __restrict__ b2,
           const float* __restrict__ fub, const float* __restrict__ bub,
           float* __restrict__ out) {
    extern __shared__ float sm[];
    float* sW  = sm;
    float* sA  = sm + 16384;
    float* sB  = sm + 24576;
    float* sFb = sm + 24704;
    float* sBb = sm + 24832;
    int tid = threadIdx.x;
    int row0 = blockIdx.x * 64;

    for (int i = tid; i < 4096; i += 128) ((float4*)sW)[i] = ((const float4*)w2)[i];
    for (int i = tid; i < 2048; i += 128)
        ((float4*)sA)[i] = ((const float4*)g_h)[(size_t)row0 * 32 + i];
    sB[tid] = b2[tid];
    { float f = fub[tid]; sFb[tid] = f > 0.f ? f : 0.f; }
    { float g = bub[tid]; sBb[tid] = g > 0.f ? g : 0.f; }
    __syncthreads();

    int ty = tid >> 4, tx = tid & 15;
    unsigned long long acc[8][4];
    gemm_tile<8>(sA, sW, ty, tx, acc);

    bool first = (row0 < P);
    bool last  = (row0 >= N_NODES - P);
#pragma unroll
    for (int i = 0; i < 8; i++) {
        int r = row0 + ty * 8 + i;
#pragma unroll
        for (int j = 0; j < 4; j++) {
            float lo, hi; up2(acc[i][j], lo, hi);
            int c = tx * 8 + 2 * j;
            lo += sB[c]; hi += sB[c + 1];
            *(float2*)&g_h[(size_t)r * 128 + c] = make_float2(lo, hi);
            if (first)
                *(float2*)&out[(size_t)r * 256 + c] = make_float2(lo + sFb[c], hi + sFb[c + 1]);
            if (last)
                *(float2*)&out[(size_t)r * 256 + 128 + c] = make_float2(lo + sBb[c], hi + sBb[c + 1]);
        }
    }
}

// ================= fused pre (fwd + bwd): m = relu(Y @ pre_w + pre_b) =================
// grid 256: blocks [0,128) forward level lf, [128,256) backward level lb
__global__ void __launch_bounds__(128, 2)
mp_pre_kernel(const float* __restrict__ out, int lf, int lb,
              const float* __restrict__ fW, const float* __restrict__ fB,
              const float* __restrict__ bW, const float* __restrict__ bB) {
    extern __shared__ float sm[];
    float* sW = sm;
    float* sA = sm + 16384;
    float* sB = sm + 24576;
    int tid = threadIdx.x;
    bool bwd = blockIdx.x >= 128;
    int row0 = (blockIdx.x & 127) * 64;
    const float* W    = bwd ? bW : fW;
    const float* bias = bwd ? bB : fB;
    const float* yin  = bwd ? out + (size_t)(lb + 1) * P * 256 + 128
                            : out + (size_t)(lf - 1) * P * 256;

    for (int i = tid; i < 4096; i += 128) ((float4*)sW)[i] = ((const float4*)W)[i];
    for (int i = tid; i < 2048; i += 128) {
        int r = i >> 5, c = i & 31;
        ((float4*)sA)[i] = *(const float4*)(yin + (size_t)(row0 + r) * 256 + c * 4);
    }
    sB[tid] = bias[tid];
    __syncthreads();

    int ty = tid >> 4, tx = tid & 15;
    unsigned long long acc[8][4];
    gemm_tile<8>(sA, sW, ty, tx, acc);
    float* mo = bwd ? g_mb : g_mf;
#pragma unroll
    for (int i = 0; i < 8; i++) {
        int r = row0 + ty * 8 + i;
#pragma unroll
        for (int j = 0; j < 4; j++) {
            float lo, hi; up2(acc[i][j], lo, hi);
            int c = tx * 8 + 2 * j;
            lo += sB[c]; hi += sB[c + 1];
            lo = lo > 0.f ? lo : 0.f; hi = hi > 0.f ? hi : 0.f;
            *(float2*)&mo[(size_t)r * 128 + c] = make_float2(lo, hi);
        }
    }
}

// ================= fused update (fwd gather + bwd CSR): relu(z@W+b) + h =================
__global__ void __launch_bounds__(128, 2)
mp_upd_kernel(const int* __restrict__ src, int lf, int lb,
              const float* __restrict__ fW, const float* __restrict__ fB,
              const float* __restrict__ bW, const float* __restrict__ bB,
              float* __restrict__ out) {
    extern __shared__ float sm[];
    float* sW = sm;
    float* sZ = sm + 16384;
    float* sB = sm + 24576;
    int*   sI = (int*)(sm + 24704);     // 512 ints (fwd) / st+cnt+rdeg (bwd)
    int tid = threadIdx.x;
    bool bwd = blockIdx.x >= 128;
    int row0 = (blockIdx.x & 127) * 64;
    const float* W    = bwd ? bW : fW;
    const float* bias = bwd ? bB : fB;

    for (int i = tid; i < 4096; i += 128) ((float4*)sW)[i] = ((const float4*)W)[i];
    sB[tid] = bias[tid];

    if (!bwd) {
        const int* srcl = src + (size_t)(lf - 1) * PK + (size_t)row0 * 8;
        for (int i = tid; i < 512; i += 128) sI[i] = srcl[i];
        __syncthreads();
        for (int idx = tid; idx < 2048; idx += 128) {
            int r = idx >> 5, c4 = idx & 31;
            const int* s8 = sI + r * 8;
            float4 v = make_float4(0.f, 0.f, 0.f, 0.f);
#pragma unroll
            for (int k = 0; k < 8; k++) {
                float4 t = *(const float4*)&g_mf[(size_t)s8[k] * 128 + c4 * 4];
                v.x += t.x; v.y += t.y; v.z += t.z; v.w += t.w;
            }
            ((float4*)sZ)[idx] = make_float4(v.x * 0.125f, v.y * 0.125f,
                                             v.z * 0.125f, v.w * 0.125f);
        }
    } else {
        int*   sSt  = sI;
        int*   sCnt = sI + 64;
        float* sRd  = (float*)(sI + 128);
        if (tid < 64) {
            int g = lb * P + row0 + tid;
            sSt[tid] = g_off[g]; sCnt[tid] = g_deg[g]; sRd[tid] = g_rdeg[g];
        }
        __syncthreads();
        const int* rev = g_rev + (size_t)lb * PK;
        for (int idx = tid; idx < 2048; idx += 128) {
            int r = idx >> 5, c4 = idx & 31;
            int st = sSt[r], n = sCnt[r];
            float4 v = make_float4(0.f, 0.f, 0.f, 0.f);
            for (int j = 0; j < n; j++) {
                float4 t = *(const float4*)&g_mb[(size_t)rev[st + j] * 128 + c4 * 4];
                v.x += t.x; v.y += t.y; v.z += t.z; v.w += t.w;
            }
            float rd = sRd[r];
            ((float4*)sZ)[idx] = make_float4(v.x * rd, v.y * rd, v.z * rd, v.w * rd);
        }
    }
    __syncthreads();

    int ty = tid >> 4, tx = tid & 15;
    unsigned long long acc[8][4];
    gemm_tile<8>(sZ, sW, ty, tx, acc);

    int level = bwd ? lb : lf;
    const float* hrow = g_h + (size_t)level * P * 128;
    float* op = out + (size_t)level * P * 256 + (bwd ? 128 : 0);
#pragma unroll
    for (int i = 0; i < 8; i++) {
        int r = row0 + ty * 8 + i;
#pragma unroll
        for (int j = 0; j < 4; j++) {
            float lo, hi; up2(acc[i][j], lo, hi);
            int c = tx * 8 + 2 * j;
            lo += sB[c]; hi += sB[c + 1];
            lo = lo > 0.f ? lo : 0.f; hi = hi > 0.f ? hi : 0.f;
            float2 h2 = *(const float2*)&hrow[(size_t)r * 128 + c];
            *(float2*)&op[(size_t)r * 256 + c] = make_float2(lo + h2.x, hi + h2.y);
        }
    }
}

// ================= launch =================
#define NT1_SMEM   98816
#define NT2_SMEM  100096
#define PRE_SMEM   98816
#define UPD_SMEM  100864

extern "C" void kernel_launch(void* const* d_in, const int* in_sizes, int n_in,
                              void* d_out, int out_size) {
    (void)in_sizes; (void)n_in; (void)out_size;
    const float* x      = (const float*)d_in[0];
    const int*   src    = (const int*)  d_in[1];
    const float* nt_w1  = (const float*)d_in[2];
    const float* nt_b1  = (const float*)d_in[3];
    const float* nt_w2  = (const float*)d_in[4];
    const float* nt_b2  = (const float*)d_in[5];
    const float* f_pre_w= (const float*)d_in[6];
    const float* f_pre_b= (const float*)d_in[7];
    const float* f_upd_w= (const float*)d_in[8];
    const float* f_upd_b= (const float*)d_in[9];
    const float* b_pre_w= (const float*)d_in[10];
    const float* b_pre_b= (const float*)d_in[11];
    const float* b_upd_w= (const float*)d_in[12];
    const float* b_upd_b= (const float*)d_in[13];
    float* out = (float*)d_out;

    cudaFuncSetAttribute(nt1_kernel,   cudaFuncAttributeMaxDynamicSharedMemorySize, NT1_SMEM);
    cudaFuncSetAttribute(nt2_kernel,   cudaFuncAttributeMaxDynamicSharedMemorySize, NT2_SMEM);
    cudaFuncSetAttribute(mp_pre_kernel, cudaFuncAttributeMaxDynamicSharedMemorySize, PRE_SMEM);
    cudaFuncSetAttribute(mp_upd_kernel, cudaFuncAttributeMaxDynamicSharedMemorySize, UPD_SMEM);

    // inverse-CSR build (ints only)
    zero_kernel <<<480, 256>>>();
    count_kernel<<<3840, 256>>>(src);
    scan_kernel <<<LM1, 256>>>();
    fill_kernel <<<3840, 256>>>(src);

    // node transform (two occ-2 passes) + level-0 fwd init + level-15 bwd init
    nt1_kernel<<<2048, 128, NT1_SMEM>>>(x, nt_w1, nt_b1);
    nt2_kernel<<<2048, 128, NT2_SMEM>>>(nt_w2, nt_b2, f_upd_b, b_upd_b, out);

    // message passing: fwd levels 1..15 and bwd levels 14..0, fused per iteration
    for (int i = 0; i < 15; i++) {
        int lf = i + 1, lb = 14 - i;
        mp_pre_kernel<<<256, 128, PRE_SMEM>>>(out, lf, lb,
                                              f_pre_w, f_pre_b, b_pre_w, b_pre_b);
        mp_upd_kernel<<<256, 128, UPD_SMEM>>>(src, lf, lb,
                                              f_upd_w, f_upd_b, b_upd_w, b_upd_b, out);
    }
}

// round 16
// speedup vs baseline: 1.6885x; 1.0188x over previous
#include <cuda_runtime.h>

// Problem constants (fixed shape for this problem)
#define N_NODES 131072
#define LVL     16
#define P       8192
#define D       128
#define KE      8
#define PK      (P*KE)     // 65536
#define LM1     (LVL-1)    // 15

// -------- scratch (static __device__ — no allocation allowed) --------
__device__ float g_h [(size_t)N_NODES * D];  // hidden, then node_transform output
__device__ float g_mf[(size_t)P * D];        // forward per-level message rows
__device__ float g_mb[(size_t)P * D];        // backward per-level message rows
__device__ int   g_deg [LM1 * P];
__device__ int   g_off [LM1 * P];
__device__ int   g_cur [LM1 * P];
__device__ float g_rdeg[LM1 * P];
__device__ int   g_rev [LM1 * PK];

// -------- packed f32x2 helpers (Blackwell FFMA2 via PTX only) --------
__device__ __forceinline__ unsigned long long pack2(float x, float y) {
    unsigned long long r;
    asm("mov.b64 %0, {%1, %2};" : "=l"(r) : "f"(x), "f"(y));
    return r;
}
__device__ __forceinline__ void up2(unsigned long long v, float& x, float& y) {
    asm("mov.b64 {%0, %1}, %2;" : "=f"(x), "=f"(y) : "l"(v));
}
__device__ __forceinline__ unsigned long long ffma2(unsigned long long a,
                                                    unsigned long long b,
                                                    unsigned long long c) {
    unsigned long long d;
    asm("fma.rn.f32x2 %0, %1, %2, %3;" : "=l"(d) : "l"(a), "l"(b), "l"(c));
    return d;
}

// -------- W smem swizzle: 16B chunk j of each 512B row stored at slot j^((j>>3)&1).
// Involution; makes the 16-lane stride-32B GEMM reads hit all 8 bank-quads (conflict-free).
#define SWZ(j) ((j) ^ (((j) >> 3) & 1))

__device__ __forceinline__ void store_w_swz(float* sW, const float* gW,
                                            int tid, int nthreads) {
    float4* d = (float4*)sW;
    const float4* s = (const float4*)gW;
    for (int i = tid; i < 4096; i += nthreads) {
        int j = i & 31;
        d[(i & ~31) | SWZ(j)] = s[i];
    }
}

// -------- shared GEMM core: tile[ROWS x 128] = sA[ROWS x 128] @ sW[128 x 128] --------
// sW must be stored with SWZ chunk swizzle. Thread layout: ty rows-of-RPT, tx in [0,16);
// each thread computes RPT rows x 8 cols (4 f32x2 pairs).
template<int RPT>
__device__ __forceinline__ void gemm_tile(const float* __restrict__ sA,
                                          const float* __restrict__ sW,
                                          int ty, int tx,
                                          unsigned long long acc[RPT][4]) {
#pragma unroll
    for (int i = 0; i < RPT; i++) {
        acc[i][0] = 0ull; acc[i][1] = 0ull; acc[i][2] = 0ull; acc[i][3] = 0ull;
    }
    const float* aBase = sA + (ty * RPT) * 128;
    int f = (tx >> 2) & 1;                       // swizzle phase for this lane
    const float* w01 = sW + (2 * tx + f) * 4;        // logical chunk 2tx
    const float* w23 = sW + (2 * tx + 1 - f) * 4;    // logical chunk 2tx+1
#pragma unroll 2
    for (int k = 0; k < 128; k += 4) {
        float4 av[RPT];
#pragma unroll
        for (int i = 0; i < RPT; i++)
            av[i] = *(const float4*)(aBase + i * 128 + k);
#pragma unroll
        for (int kk = 0; kk < 4; kk++) {
            int o = (k + kk) * 128;
            ulonglong2 b01 = *(const ulonglong2*)(w01 + o);
            ulonglong2 b23 = *(const ulonglong2*)(w23 + o);
#pragma unroll
            for (int i = 0; i < RPT; i++) {
                float a = (kk == 0) ? av[i].x : (kk == 1) ? av[i].y
                         : (kk == 2) ? av[i].z : av[i].w;
                unsigned long long aa = pack2(a, a);
                acc[i][0] = ffma2(aa, b01.x, acc[i][0]);
                acc[i][1] = ffma2(aa, b01.y, acc[i][1]);
                acc[i][2] = ffma2(aa, b23.x, acc[i][2]);
                acc[i][3] = ffma2(aa, b23.y, acc[i][3]);
            }
        }
    }
}

// ================= CSR build (once per call, replayed in graph) =================
__global__ void zero_kernel() {
    int i = blockIdx.x * blockDim.x + threadIdx.x;
    if (i < LM1 * P) g_deg[i] = 0;
}
// 4 edges per thread (int4) for MLP on the L2 atomics. LM1*PK = 983040 = 960*256*4.
__global__ void count_kernel(const int* __restrict__ src) {
    int e = (blockIdx.x * blockDim.x + threadIdx.x) * 4;
    int l = e >> 16;                       // 65536 % 4 == 0: no straddle
    int4 s = *(const int4*)(src + e);
    atomicAdd(&g_deg[l * P + s.x], 1);
    atomicAdd(&g_deg[l * P + s.y], 1);
    atomicAdd(&g_deg[l * P + s.z], 1);
    atomicAdd(&g_deg[l * P + s.w], 1);
}
__global__ void scan_kernel() {
    int l = blockIdx.x, t = threadIdx.x;   // 256 threads, 8192 entries
    __shared__ int ss[256];
    int base = l * P + t * 32;
    int loc[32]; int s = 0;
#pragma unroll
    for (int i = 0; i < 32; i++) { loc[i] = g_deg[base + i]; s += loc[i]; }
    ss[t] = s; __syncthreads();
    if (t == 0) { int run = 0; for (int i = 0; i < 256; i++) { int v = ss[i]; ss[i] = run; run += v; } }
    __syncthreads();
    int run = ss[t];
#pragma unroll
    for (int i = 0; i < 32; i++) {
        g_off[base + i] = run;
        g_cur[base + i] = run;
        int d = loc[i];
        g_rdeg[base + i] = 1.0f / (float)(d > 0 ? d : 1);
        run += d;
    }
}
__global__ void fill_kernel(const int* __restrict__ src) {
    int e = (blockIdx.x * blockDim.x + threadIdx.x) * 4;
    int l = e >> 16;
    int4 s = *(const int4*)(src + e);
    int le = e & 65535;
    int s0 = atomicAdd(&g_cur[l * P + s.x], 1);
    int s1 = atomicAdd(&g_cur[l * P + s.y], 1);
    int s2 = atomicAdd(&g_cur[l * P + s.z], 1);
    int s3 = atomicAdd(&g_cur[l * P + s.w], 1);
    g_rev[l * PK + s0] = (le + 0) >> 3;   // dst node = edge/K
    g_rev[l * PK + s1] = (le + 1) >> 3;
    g_rev[l * PK + s2] = (le + 2) >> 3;
    g_rev[l * PK + s3] = (le + 3) >> 3;
}

// ================= nt pass 1: g_h = relu(x @ W1 + b1) =================
__global__ void __launch_bounds__(128, 2)
nt1_kernel(const float* __restrict__ x,
           const float* __restrict__ w1, const float* __restrict__ b1) {
    extern __shared__ float sm[];
    float* sW = sm;            // 16384 floats (swizzled)
    float* sA = sm + 16384;    // 8192
    float* sB = sm + 24576;    // 128
    int tid = threadIdx.x;
    int row0 = blockIdx.x * 64;

    store_w_swz(sW, w1, tid, 128);
    for (int i = tid; i < 2048; i += 128)
        ((float4*)sA)[i] = ((const float4*)x)[(size_t)row0 * 32 + i];
    sB[tid] = b1[tid];
    __syncthreads();

    int ty = tid >> 4, tx = tid & 15;
    unsigned long long acc[8][4];
    gemm_tile<8>(sA, sW, ty, tx, acc);
#pragma unroll
    for (int i = 0; i < 8; i++) {
        int r = row0 + ty * 8 + i;
#pragma unroll
        for (int j = 0; j < 4; j++) {
            float lo, hi; up2(acc[i][j], lo, hi);
            int c = tx * 8 + 2 * j;
            lo += sB[c]; hi += sB[c + 1];
            lo = lo > 0.f ? lo : 0.f; hi = hi > 0.f ? hi : 0.f;
            *(float2*)&g_h[(size_t)r * 128 + c] = make_float2(lo, hi);
        }
    }
}

// ================= nt pass 2: g_h = g_h @ W2 + b2 (in place), plus out inits =================
__global__ void __launch_bounds__(128, 2)
nt2_kernel(const float* __restrict__ w2, const float* __restrict__ b2,
           const float* __restrict__ fub, const float* __restrict__ bub,
           float* __restrict__ out) {
    extern __shared__ float sm[];
    float* sW  = sm;
    float* sA  = sm + 16384;
    float* sB  = sm + 24576;
    float* sFb = sm + 24704;
    float* sBb = sm + 24832;
    int tid = threadIdx.x;
    int row0 = blockIdx.x * 64;

    store_w_swz(sW, w2, tid, 128);
    for (int i = tid; i < 2048; i += 128)
        ((float4*)sA)[i] = ((const float4*)g_h)[(size_t)row0 * 32 + i];
    sB[tid] = b2[tid];
    { float f = fub[tid]; sFb[tid] = f > 0.f ? f : 0.f; }
    { float g = bub[tid]; sBb[tid] = g > 0.f ? g : 0.f; }
    __syncthreads();

    int ty = tid >> 4, tx = tid & 15;
    unsigned long long acc[8][4];
    gemm_tile<8>(sA, sW, ty, tx, acc);

    bool first = (row0 < P);
    bool last  = (row0 >= N_NODES - P);
#pragma unroll
    for (int i = 0; i < 8; i++) {
        int r = row0 + ty * 8 + i;
#pragma unroll
        for (int j = 0; j < 4; j++) {
            float lo, hi; up2(acc[i][j], lo, hi);
            int c = tx * 8 + 2 * j;
            lo += sB[c]; hi += sB[c + 1];
            *(float2*)&g_h[(size_t)r * 128 + c] = make_float2(lo, hi);
            if (first)
                *(float2*)&out[(size_t)r * 256 + c] = make_float2(lo + sFb[c], hi + sFb[c + 1]);
            if (last)
                *(float2*)&out[(size_t)r * 256 + 128 + c] = make_float2(lo + sBb[c], hi + sBb[c + 1]);
        }
    }
}

// ================= fused pre (fwd + bwd): m = relu(Y @ pre_w + pre_b) =================
// grid 256: blocks [0,128) forward level lf, [128,256) backward level lb
__global__ void __launch_bounds__(128, 2)
mp_pre_kernel(const float* __restrict__ out, int lf, int lb,
              const float* __restrict__ fW, const float* __restrict__ fB,
              const float* __restrict__ bW, const float* __restrict__ bB) {
    extern __shared__ float sm[];
    float* sW = sm;
    float* sA = sm + 16384;
    float* sB = sm + 24576;
    int tid = threadIdx.x;
    bool bwd = blockIdx.x >= 128;
    int row0 = (blockIdx.x & 127) * 64;
    const float* W    = bwd ? bW : fW;
    const float* bias = bwd ? bB : fB;
    const float* yin  = bwd ? out + (size_t)(lb + 1) * P * 256 + 128
                            : out + (size_t)(lf - 1) * P * 256;

    store_w_swz(sW, W, tid, 128);
    for (int i = tid; i < 2048; i += 128) {
        int r = i >> 5, c = i & 31;
        ((float4*)sA)[i] = *(const float4*)(yin + (size_t)(row0 + r) * 256 + c * 4);
    }
    sB[tid] = bias[tid];
    __syncthreads();

    int ty = tid >> 4, tx = tid & 15;
    unsigned long long acc[8][4];
    gemm_tile<8>(sA, sW, ty, tx, acc);
    float* mo = bwd ? g_mb : g_mf;
#pragma unroll
    for (int i = 0; i < 8; i++) {
        int r = row0 + ty * 8 + i;
#pragma unroll
        for (int j = 0; j < 4; j++) {
            float lo, hi; up2(acc[i][j], lo, hi);
            int c = tx * 8 + 2 * j;
            lo += sB[c]; hi += sB[c + 1];
            lo = lo > 0.f ? lo : 0.f; hi = hi > 0.f ? hi : 0.f;
            *(float2*)&mo[(size_t)r * 128 + c] = make_float2(lo, hi);
        }
    }
}

// ================= fused update (fwd gather + bwd CSR): relu(z@W+b) + h =================
__global__ void __launch_bounds__(128, 2)
mp_upd_kernel(const int* __restrict__ src, int lf, int lb,
              const float* __restrict__ fW, const float* __restrict__ fB,
              const float* __restrict__ bW, const float* __restrict__ bB,
              float* __restrict__ out) {
    extern __shared__ float sm[];
    float* sW = sm;
    float* sZ = sm + 16384;
    float* sB = sm + 24576;
    int*   sI = (int*)(sm + 24704);     // 512 ints (fwd) / st+cnt+rdeg (bwd)
    int tid = threadIdx.x;
    bool bwd = blockIdx.x >= 128;
    int row0 = (blockIdx.x & 127) * 64;
    const float* W    = bwd ? bW : fW;
    const float* bias = bwd ? bB : fB;

    store_w_swz(sW, W, tid, 128);
    sB[tid] = bias[tid];

    if (!bwd) {
        const int* srcl = src + (size_t)(lf - 1) * PK + (size_t)row0 * 8;
        for (int i = tid; i < 512; i += 128) sI[i] = srcl[i];
        __syncthreads();
        for (int idx = tid; idx < 2048; idx += 128) {
            int r = idx >> 5, c4 = idx & 31;
            const int* s8 = sI + r * 8;
            float4 v = make_float4(0.f, 0.f, 0.f, 0.f);
#pragma unroll
            for (int k = 0; k < 8; k++) {
                float4 t = *(const float4*)&g_mf[(size_t)s8[k] * 128 + c4 * 4];
                v.x += t.x; v.y += t.y; v.z += t.z; v.w += t.w;
            }
            ((float4*)sZ)[idx] = make_float4(v.x * 0.125f, v.y * 0.125f,
                                             v.z * 0.125f, v.w * 0.125f);
        }
    } else {
        int*   sSt  = sI;
        int*   sCnt = sI + 64;
        float* sRd  = (float*)(sI + 128);
        if (tid < 64) {
            int g = lb * P + row0 + tid;
            sSt[tid] = g_off[g]; sCnt[tid] = g_deg[g]; sRd[tid] = g_rdeg[g];
        }
        __syncthreads();
        const int* rev = g_rev + (size_t)lb * PK;
        for (int idx = tid; idx < 2048; idx += 128) {
            int r = idx >> 5, c4 = idx & 31;
            int st = sSt[r], n = sCnt[r];
            float4 v = make_float4(0.f, 0.f, 0.f, 0.f);
            for (int j = 0; j < n; j++) {
                float4 t = *(const float4*)&g_mb[(size_t)rev[st + j] * 128 + c4 * 4];
                v.x += t.x; v.y += t.y; v.z += t.z; v.w += t.w;
            }
            float rd = sRd[r];
            ((float4*)sZ)[idx] = make_float4(v.x * rd, v.y * rd, v.z * rd, v.w * rd);
        }
    }
    __syncthreads();

    int ty = tid >> 4, tx = tid & 15;
    unsigned long long acc[8][4];
    gemm_tile<8>(sZ, sW, ty, tx, acc);

    int level = bwd ? lb : lf;
    const float* hrow = g_h + (size_t)level * P * 128;
    float* op = out + (size_t)level * P * 256 + (bwd ? 128 : 0);
#pragma unroll
    for (int i = 0; i < 8; i++) {
        int r = row0 + ty * 8 + i;
#pragma unroll
        for (int j = 0; j < 4; j++) {
            float lo, hi; up2(acc[i][j], lo, hi);
            int c = tx * 8 + 2 * j;
            lo += sB[c]; hi += sB[c + 1];
            lo = lo > 0.f ? lo : 0.f; hi = hi > 0.f ? hi : 0.f;
            float2 h2 = *(const float2*)&hrow[(size_t)r * 128 + c];
            *(float2*)&op[(size_t)r * 256 + c] = make_float2(lo + h2.x, hi + h2.y);
        }
    }
}

// ================= launch =================
#define NT1_SMEM   98816
#define NT2_SMEM  100096
#define PRE_SMEM   98816
#define UPD_SMEM  100864

extern "C" void kernel_launch(void* const* d_in, const int* in_sizes, int n_in,
                              void* d_out, int out_size) {
    (void)in_sizes; (void)n_in; (void)out_size;
    const float* x      = (const float*)d_in[0];
    const int*   src    = (const int*)  d_in[1];
    const float* nt_w1  = (const float*)d_in[2];
    const float* nt_b1  = (const float*)d_in[3];
    const float* nt_w2  = (const float*)d_in[4];
    const float* nt_b2  = (const float*)d_in[5];
    const float* f_pre_w= (const float*)d_in[6];
    const float* f_pre_b= (const float*)d_in[7];
    const float* f_upd_w= (const float*)d_in[8];
    const float* f_upd_b= (const float*)d_in[9];
    const float* b_pre_w= (const float*)d_in[10];
    const float* b_pre_b= (const float*)d_in[11];
    const float* b_upd_w= (const float*)d_in[12];
    const float* b_upd_b= (const float*)d_in[13];
    float* out = (float*)d_out;

    cudaFuncSetAttribute(nt1_kernel,   cudaFuncAttributeMaxDynamicSharedMemorySize, NT1_SMEM);
    cudaFuncSetAttribute(nt2_kernel,   cudaFuncAttributeMaxDynamicSharedMemorySize, NT2_SMEM);
    cudaFuncSetAttribute(mp_pre_kernel, cudaFuncAttributeMaxDynamicSharedMemorySize, PRE_SMEM);
    cudaFuncSetAttribute(mp_upd_kernel, cudaFuncAttributeMaxDynamicSharedMemorySize, UPD_SMEM);

    // inverse-CSR build (ints only)
    zero_kernel <<<480, 256>>>();
    count_kernel<<<960, 256>>>(src);
    scan_kernel <<<LM1, 256>>>();
    fill_kernel <<<960, 256>>>(src);

    // node transform (two occ-2 passes) + level-0 fwd init + level-15 bwd init
    nt1_kernel<<<2048, 128, NT1_SMEM>>>(x, nt_w1, nt_b1);
    nt2_kernel<<<2048, 128, NT2_SMEM>>>(nt_w2, nt_b2, f_upd_b, b_upd_b, out);

    // message passing: fwd levels 1..15 and bwd levels 14..0, fused per iteration
    for (int i = 0; i < 15; i++) {
        int lf = i + 1, lb = 14 - i;
        mp_pre_kernel<<<256, 128, PRE_SMEM>>>(out, lf, lb,
                                              f_pre_w, f_pre_b, b_pre_w, b_pre_b);
        mp_upd_kernel<<<256, 128, UPD_SMEM>>>(src, lf, lb,
                                              f_upd_w, f_upd_b, b_upd_w, b_upd_b, out);
    }
}

// round 17
// speedup vs baseline: 1.6970x; 1.0050x over previous
#include <cuda_runtime.h>

// Problem constants (fixed shape for this problem)
#define N_NODES 131072
#define LVL     16
#define P       8192
#define D       128
#define KE      8
#define PK      (P*KE)     // 65536
#define LM1     (LVL-1)    // 15

// -------- scratch (static __device__ — no allocation allowed) --------
__device__ float g_h [(size_t)N_NODES * D];  // hidden, then node_transform output
__device__ float g_mf[(size_t)P * D];        // forward per-level message rows
__device__ float g_mb[(size_t)P * D];        // backward per-level message rows
__device__ int   g_deg [LM1 * P];
__device__ int   g_off [LM1 * P];
__device__ int   g_cur [LM1 * P];
__device__ float g_rdeg[LM1 * P];
__device__ int   g_rev [LM1 * PK];

// -------- packed f32x2 helpers (Blackwell FFMA2 via PTX only) --------
__device__ __forceinline__ unsigned long long pack2(float x, float y) {
    unsigned long long r;
    asm("mov.b64 %0, {%1, %2};" : "=l"(r) : "f"(x), "f"(y));
    return r;
}
__device__ __forceinline__ void up2(unsigned long long v, float& x, float& y) {
    asm("mov.b64 {%0, %1}, %2;" : "=f"(x), "=f"(y) : "l"(v));
}
__device__ __forceinline__ unsigned long long ffma2(unsigned long long a,
                                                    unsigned long long b,
                                                    unsigned long long c) {
    unsigned long long d;
    asm("fma.rn.f32x2 %0, %1, %2, %3;" : "=l"(d) : "l"(a), "l"(b), "l"(c));
    return d;
}

// -------- W smem swizzle: 16B chunk j of each 512B row stored at slot j^((j>>3)&1).
// Involution; makes the 16-lane stride-32B GEMM reads hit all 8 bank-quads (conflict-free).
#define SWZ(j) ((j) ^ (((j) >> 3) & 1))

__device__ __forceinline__ void store_w_swz(float* sW, const float* gW,
                                            int tid, int nthreads) {
    float4* d = (float4*)sW;
    const float4* s = (const float4*)gW;
    for (int i = tid; i < 4096; i += nthreads) {
        int j = i & 31;
        d[(i & ~31) | SWZ(j)] = s[i];
    }
}

// -------- shared GEMM core: tile[ROWS x 128] = sA[ROWS x 128] @ sW[128 x 128] --------
// sW must be stored with SWZ chunk swizzle. Thread layout: ty rows-of-RPT, tx in [0,16);
// each thread computes RPT rows x 8 cols (4 f32x2 pairs).
template<int RPT>
__device__ __forceinline__ void gemm_tile(const float* __restrict__ sA,
                                          const float* __restrict__ sW,
                                          int ty, int tx,
                                          unsigned long long acc[RPT][4]) {
#pragma unroll
    for (int i = 0; i < RPT; i++) {
        acc[i][0] = 0ull; acc[i][1] = 0ull; acc[i][2] = 0ull; acc[i][3] = 0ull;
    }
    const float* aBase = sA + (ty * RPT) * 128;
    int f = (tx >> 2) & 1;                       // swizzle phase for this lane
    const float* w01 = sW + (2 * tx + f) * 4;        // logical chunk 2tx
    const float* w23 = sW + (2 * tx + 1 - f) * 4;    // logical chunk 2tx+1
#pragma unroll 2
    for (int k = 0; k < 128; k += 4) {
        float4 av[RPT];
#pragma unroll
        for (int i = 0; i < RPT; i++)
            av[i] = *(const float4*)(aBase + i * 128 + k);
#pragma unroll
        for (int kk = 0; kk < 4; kk++) {
            int o = (k + kk) * 128;
            ulonglong2 b01 = *(const ulonglong2*)(w01 + o);
            ulonglong2 b23 = *(const ulonglong2*)(w23 + o);
#pragma unroll
            for (int i = 0; i < RPT; i++) {
                float a = (kk == 0) ? av[i].x : (kk == 1) ? av[i].y
                         : (kk == 2) ? av[i].z : av[i].w;
                unsigned long long aa = pack2(a, a);
                acc[i][0] = ffma2(aa, b01.x, acc[i][0]);
                acc[i][1] = ffma2(aa, b01.y, acc[i][1]);
                acc[i][2] = ffma2(aa, b23.x, acc[i][2]);
                acc[i][3] = ffma2(aa, b23.y, acc[i][3]);
            }
        }
    }
}

// ================= CSR build (once per call, replayed in graph) =================
__global__ void zero_kernel() {
    int i = blockIdx.x * blockDim.x + threadIdx.x;
    if (i < LM1 * P) g_deg[i] = 0;
}
// 4 edges per thread (int4) for MLP on the L2 atomics. LM1*PK = 983040 = 960*256*4.
__global__ void count_kernel(const int* __restrict__ src) {
    int e = (blockIdx.x * blockDim.x + threadIdx.x) * 4;
    int l = e >> 16;                       // 65536 % 4 == 0: no straddle
    int4 s = *(const int4*)(src + e);
    atomicAdd(&g_deg[l * P + s.x], 1);
    atomicAdd(&g_deg[l * P + s.y], 1);
    atomicAdd(&g_deg[l * P + s.z], 1);
    atomicAdd(&g_deg[l * P + s.w], 1);
}
__global__ void scan_kernel() {
    int l = blockIdx.x, t = threadIdx.x;   // 256 threads, 8192 entries
    __shared__ int ss[256];
    int base = l * P + t * 32;
    int loc[32]; int s = 0;
#pragma unroll
    for (int i = 0; i < 32; i++) { loc[i] = g_deg[base + i]; s += loc[i]; }
    ss[t] = s; __syncthreads();
    if (t == 0) { int run = 0; for (int i = 0; i < 256; i++) { int v = ss[i]; ss[i] = run; run += v; } }
    __syncthreads();
    int run = ss[t];
#pragma unroll
    for (int i = 0; i < 32; i++) {
        g_off[base + i] = run;
        g_cur[base + i] = run;
        int d = loc[i];
        g_rdeg[base + i] = 1.0f / (float)(d > 0 ? d : 1);
        run += d;
    }
}
__global__ void fill_kernel(const int* __restrict__ src) {
    int e = (blockIdx.x * blockDim.x + threadIdx.x) * 4;
    int l = e >> 16;
    int4 s = *(const int4*)(src + e);
    int le = e & 65535;
    int s0 = atomicAdd(&g_cur[l * P + s.x], 1);
    int s1 = atomicAdd(&g_cur[l * P + s.y], 1);
    int s2 = atomicAdd(&g_cur[l * P + s.z], 1);
    int s3 = atomicAdd(&g_cur[l * P + s.w], 1);
    g_rev[l * PK + s0] = (le + 0) >> 3;   // dst node = edge/K
    g_rev[l * PK + s1] = (le + 1) >> 3;
    g_rev[l * PK + s2] = (le + 2) >> 3;
    g_rev[l * PK + s3] = (le + 3) >> 3;
}

// ================= nt pass 1: g_h = relu(x @ W1 + b1) =================
__global__ void __launch_bounds__(128, 2)
nt1_kernel(const float* __restrict__ x,
           const float* __restrict__ w1, const float* __restrict__ b1) {
    extern __shared__ float sm[];
    float* sW = sm;            // 16384 floats (swizzled)
    float* sA = sm + 16384;    // 8192
    float* sB = sm + 24576;    // 128
    int tid = threadIdx.x;
    int row0 = blockIdx.x * 64;

    store_w_swz(sW, w1, tid, 128);
    for (int i = tid; i < 2048; i += 128)
        ((float4*)sA)[i] = ((const float4*)x)[(size_t)row0 * 32 + i];
    sB[tid] = b1[tid];
    __syncthreads();

    int ty = tid >> 4, tx = tid & 15;
    unsigned long long acc[8][4];
    gemm_tile<8>(sA, sW, ty, tx, acc);
#pragma unroll
    for (int i = 0; i < 8; i++) {
        int r = row0 + ty * 8 + i;
#pragma unroll
        for (int j = 0; j < 4; j++) {
            float lo, hi; up2(acc[i][j], lo, hi);
            int c = tx * 8 + 2 * j;
            lo += sB[c]; hi += sB[c + 1];
            lo = lo > 0.f ? lo : 0.f; hi = hi > 0.f ? hi : 0.f;
            *(float2*)&g_h[(size_t)r * 128 + c] = make_float2(lo, hi);
        }
    }
}

// ================= nt pass 2: g_h = g_h @ W2 + b2 (in place), plus out inits =================
__global__ void __launch_bounds__(128, 2)
nt2_kernel(const float* __restrict__ w2, const float* __restrict__ b2,
           const float* __restrict__ fub, const float* __restrict__ bub,
           float* __restrict__ out) {
    extern __shared__ float sm[];
    float* sW  = sm;
    float* sA  = sm + 16384;
    float* sB  = sm + 24576;
    float* sFb = sm + 24704;
    float* sBb = sm + 24832;
    int tid = threadIdx.x;
    int row0 = blockIdx.x * 64;

    store_w_swz(sW, w2, tid, 128);
    for (int i = tid; i < 2048; i += 128)
        ((float4*)sA)[i] = ((const float4*)g_h)[(size_t)row0 * 32 + i];
    sB[tid] = b2[tid];
    { float f = fub[tid]; sFb[tid] = f > 0.f ? f : 0.f; }
    { float g = bub[tid]; sBb[tid] = g > 0.f ? g : 0.f; }
    __syncthreads();

    int ty = tid >> 4, tx = tid & 15;
    unsigned long long acc[8][4];
    gemm_tile<8>(sA, sW, ty, tx, acc);

    bool first = (row0 < P);
    bool last  = (row0 >= N_NODES - P);
#pragma unroll
    for (int i = 0; i < 8; i++) {
        int r = row0 + ty * 8 + i;
#pragma unroll
        for (int j = 0; j < 4; j++) {
            float lo, hi; up2(acc[i][j], lo, hi);
            int c = tx * 8 + 2 * j;
            lo += sB[c]; hi += sB[c + 1];
            *(float2*)&g_h[(size_t)r * 128 + c] = make_float2(lo, hi);
            if (first)
                *(float2*)&out[(size_t)r * 256 + c] = make_float2(lo + sFb[c], hi + sFb[c + 1]);
            if (last)
                *(float2*)&out[(size_t)r * 256 + 128 + c] = make_float2(lo + sBb[c], hi + sBb[c + 1]);
        }
    }
}

// ================= fused pre (fwd + bwd): m = relu(Y @ pre_w + pre_b) =================
// grid 256: blocks [0,128) forward level lf, [128,256) backward level lb
__global__ void __launch_bounds__(128, 2)
mp_pre_kernel(const float* __restrict__ out, int lf, int lb,
              const float* __restrict__ fW, const float* __restrict__ fB,
              const float* __restrict__ bW, const float* __restrict__ bB) {
    extern __shared__ float sm[];
    float* sW = sm;
    float* sA = sm + 16384;
    float* sB = sm + 24576;
    int tid = threadIdx.x;
    bool bwd = blockIdx.x >= 128;
    int row0 = (blockIdx.x & 127) * 64;
    const float* W    = bwd ? bW : fW;
    const float* bias = bwd ? bB : fB;
    const float* yin  = bwd ? out + (size_t)(lb + 1) * P * 256 + 128
                            : out + (size_t)(lf - 1) * P * 256;

    store_w_swz(sW, W, tid, 128);
    for (int i = tid; i < 2048; i += 128) {
        int r = i >> 5, c = i & 31;
        ((float4*)sA)[i] = *(const float4*)(yin + (size_t)(row0 + r) * 256 + c * 4);
    }
    sB[tid] = bias[tid];
    __syncthreads();

    int ty = tid >> 4, tx = tid & 15;
    unsigned long long acc[8][4];
    gemm_tile<8>(sA, sW, ty, tx, acc);
    float* mo = bwd ? g_mb : g_mf;
#pragma unroll
    for (int i = 0; i < 8; i++) {
        int r = row0 + ty * 8 + i;
#pragma unroll
        for (int j = 0; j < 4; j++) {
            float lo, hi; up2(acc[i][j], lo, hi);
            int c = tx * 8 + 2 * j;
            lo += sB[c]; hi += sB[c + 1];
            lo = lo > 0.f ? lo : 0.f; hi = hi > 0.f ? hi : 0.f;
            *(float2*)&mo[(size_t)r * 128 + c] = make_float2(lo, hi);
        }
    }
}

// ================= fused update (fwd gather + bwd CSR): relu(z@W+b) + h =================
__global__ void __launch_bounds__(128, 2)
mp_upd_kernel(const int* __restrict__ src, int lf, int lb,
              const float* __restrict__ fW, const float* __restrict__ fB,
              const float* __restrict__ bW, const float* __restrict__ bB,
              float* __restrict__ out) {
    extern __shared__ float sm[];
    float* sW = sm;
    float* sZ = sm + 16384;
    float* sB = sm + 24576;
    int*   sI = (int*)(sm + 24704);     // 512 ints (fwd) / st+cnt+rdeg (bwd)
    int tid = threadIdx.x;
    bool bwd = blockIdx.x >= 128;
    int row0 = (blockIdx.x & 127) * 64;
    const float* W    = bwd ? bW : fW;
    const float* bias = bwd ? bB : fB;

    store_w_swz(sW, W, tid, 128);
    sB[tid] = bias[tid];

    if (!bwd) {
        const int* srcl = src + (size_t)(lf - 1) * PK + (size_t)row0 * 8;
        for (int i = tid; i < 512; i += 128) sI[i] = srcl[i];
        __syncthreads();
        for (int idx = tid; idx < 2048; idx += 128) {
            int r = idx >> 5, c4 = idx & 31;
            const int* s8 = sI + r * 8;
            float4 v = make_float4(0.f, 0.f, 0.f, 0.f);
#pragma unroll
            for (int k = 0; k < 8; k++) {
                float4 t = *(const float4*)&g_mf[(size_t)s8[k] * 128 + c4 * 4];
                v.x += t.x; v.y += t.y; v.z += t.z; v.w += t.w;
            }
            ((float4*)sZ)[idx] = make_float4(v.x * 0.125f, v.y * 0.125f,
                                             v.z * 0.125f, v.w * 0.125f);
        }
    } else {
        int*   sSt  = sI;
        int*   sCnt = sI + 64;
        float* sRd  = (float*)(sI + 128);
        if (tid < 64) {
            int g = lb * P + row0 + tid;
            sSt[tid] = g_off[g]; sCnt[tid] = g_deg[g]; sRd[tid] = g_rdeg[g];
        }
        __syncthreads();
        const int* rev = g_rev + (size_t)lb * PK;
        for (int idx = tid; idx < 2048; idx += 128) {
            int r = idx >> 5, c4 = idx & 31;
            int st = sSt[r], n = sCnt[r];
            float4 v = make_float4(0.f, 0.f, 0.f, 0.f);
            for (int j = 0; j < n; j++) {
                float4 t = *(const float4*)&g_mb[(size_t)rev[st + j] * 128 + c4 * 4];
                v.x += t.x; v.y += t.y; v.z += t.z; v.w += t.w;
            }
            float rd = sRd[r];
            ((float4*)sZ)[idx] = make_float4(v.x * rd, v.y * rd, v.z * rd, v.w * rd);
        }
    }
    __syncthreads();

    int ty = tid >> 4, tx = tid & 15;
    unsigned long long acc[8][4];
    gemm_tile<8>(sZ, sW, ty, tx, acc);

    int level = bwd ? lb : lf;
    const float* hrow = g_h + (size_t)level * P * 128;
    float* op = out + (size_t)level * P * 256 + (bwd ? 128 : 0);
#pragma unroll
    for (int i = 0; i < 8; i++) {
        int r = row0 + ty * 8 + i;
#pragma unroll
        for (int j = 0; j < 4; j++) {
            float lo, hi; up2(acc[i][j], lo, hi);
            int c = tx * 8 + 2 * j;
            lo += sB[c]; hi += sB[c + 1];
            lo = lo > 0.f ? lo : 0.f; hi = hi > 0.f ? hi : 0.f;
            float2 h2 = *(const float2*)&hrow[(size_t)r * 128 + c];
            *(float2*)&op[(size_t)r * 256 + c] = make_float2(lo + h2.x, hi + h2.y);
        }
    }
}

// ================= launch =================
#define NT1_SMEM   98816
#define NT2_SMEM  100096
#define PRE_SMEM   98816
#define UPD_SMEM  100864

extern "C" void kernel_launch(void* const* d_in, const int* in_sizes, int n_in,
                              void* d_out, int out_size) {
    (void)in_sizes; (void)n_in; (void)out_size;
    const float* x      = (const float*)d_in[0];
    const int*   src    = (const int*)  d_in[1];
    const float* nt_w1  = (const float*)d_in[2];
    const float* nt_b1  = (const float*)d_in[3];
    const float* nt_w2  = (const float*)d_in[4];
    const float* nt_b2  = (const float*)d_in[5];
    const float* f_pre_w= (const float*)d_in[6];
    const float* f_pre_b= (const float*)d_in[7];
    const float* f_upd_w= (const float*)d_in[8];
    const float* f_upd_b= (const float*)d_in[9];
    const float* b_pre_w= (const float*)d_in[10];
    const float* b_pre_b= (const float*)d_in[11];
    const float* b_upd_w= (const float*)d_in[12];
    const float* b_upd_b= (const float*)d_in[13];
    float* out = (float*)d_out;

    cudaFuncSetAttribute(nt1_kernel,   cudaFuncAttributeMaxDynamicSharedMemorySize, NT1_SMEM);
    cudaFuncSetAttribute(nt2_kernel,   cudaFuncAttributeMaxDynamicSharedMemorySize, NT2_SMEM);
    cudaFuncSetAttribute(mp_pre_kernel, cudaFuncAttributeMaxDynamicSharedMemorySize, PRE_SMEM);
    cudaFuncSetAttribute(mp_upd_kernel, cudaFuncAttributeMaxDynamicSharedMemorySize, UPD_SMEM);

    // inverse-CSR build (ints only)
    zero_kernel <<<480, 256>>>();
    count_kernel<<<960, 256>>>(src);
    scan_kernel <<<LM1, 256>>>();
    fill_kernel <<<960, 256>>>(src);

    // node transform (two occ-2 passes) + level-0 fwd init + level-15 bwd init
    nt1_kernel<<<2048, 128, NT1_SMEM>>>(x, nt_w1, nt_b1);
    nt2_kernel<<<2048, 128, NT2_SMEM>>>(nt_w2, nt_b2, f_upd_b, b_upd_b, out);

    // message passing: fwd levels 1..15 and bwd levels 14..0, fused per iteration
    for (int i = 0; i < 15; i++) {
        int lf = i + 1, lb = 14 - i;
        mp_pre_kernel<<<256, 128, PRE_SMEM>>>(out, lf, lb,
                                              f_pre_w, f_pre_b, b_pre_w, b_pre_b);
        mp_upd_kernel<<<256, 128, UPD_SMEM>>>(src, lf, lb,
                                              f_upd_w, f_upd_b, b_upd_w, b_upd_b, out);
    }
}